// round 7
// baseline (speedup 1.0000x reference)
#include <cuda_runtime.h>
#include <cuda_bf16.h>

// DTW 2048x2048 anti-diagonal wavefront, 2-CTA cluster, one CTA per SM.
// CTA c owns rows [1024c, 1024c+1024): 8 warps x 32 lanes x 4 rows/thread.
// Per-CTA engine = the measured-good R2 scalar pipeline (smem ring +
// cta-scope acquire/release counters). Cross-CTA boundary fixes vs R4:
//   * boundary ring = 1024 entries (~32 batches of elasticity) so stale
//     backpressure info can never lock-step the CTAs (R4 used 64 -> serial).
//   * KB=32 diagonals per batch -> boundary fence/publish half as frequent.
//   * cluster-scope ops confined to the 2 boundary warps, one release store
//     and (consumer only) one acq_rel fence per 32 diagonals.
// Cell recurrence (rows r=0..3 per thread):
//   n[r] = (x[r]-y[d-i0-r])^2 + min(up, left, diag), all register-resident
// except each warp's top row (shfl_up + ring). Out-of-range cells stay +inf
// (left) or finite garbage flowing only rightward (right): no predicates.

#define NLEN  2048
#define NC    2
#define NW    8
#define RPT   4
#define KB    32
#define NB    127           // full batches (127*32 = 4064)
#define TAIL  31            // 4064 + 31 = 4095 diagonals
#define SRING 128           // intra-CTA ring (entries)
#define BRING 1024          // cross-CTA boundary ring (entries)
#define FINF  __int_as_float(0x7f800000)

__device__ __forceinline__ unsigned smem_u32(const void* p) {
    return (unsigned)__cvta_generic_to_shared(p);
}
__device__ __forceinline__ unsigned mapa_u32(unsigned addr, unsigned rank) {
    unsigned r;
    asm("mapa.shared::cluster.u32 %0, %1, %2;" : "=r"(r) : "r"(addr), "r"(rank));
    return r;
}
__device__ __forceinline__ int ld_acq_cta(const int* p) {
    int v; unsigned a = smem_u32(p);
    asm volatile("ld.acquire.cta.shared::cta.b32 %0, [%1];" : "=r"(v) : "r"(a) : "memory");
    return v;
}
__device__ __forceinline__ int ld_rlx_cluster(const int* p) {
    int v; unsigned a = smem_u32(p);
    asm volatile("ld.relaxed.cluster.shared::cta.b32 %0, [%1];" : "=r"(v) : "r"(a) : "memory");
    return v;
}
__device__ __forceinline__ void fence_acq_cluster() {
    asm volatile("fence.acq_rel.cluster;" ::: "memory");
}
__device__ __forceinline__ void st_rel_cta(int* p, int v) {
    unsigned a = smem_u32(p);
    asm volatile("st.release.cta.shared::cta.b32 [%0], %1;" :: "r"(a), "r"(v) : "memory");
}
__device__ __forceinline__ void st_rel_cluster_rem(unsigned a, int v) {
    asm volatile("st.release.cluster.shared::cluster.b32 [%0], %1;" :: "r"(a), "r"(v) : "memory");
}
__device__ __forceinline__ void st_f32_rem(unsigned a, float v) {
    asm volatile("st.shared::cluster.f32 [%0], %1;" :: "r"(a), "f"(v) : "memory");
}
__device__ __forceinline__ void cluster_sync_() {
    asm volatile("barrier.cluster.arrive.aligned;" ::: "memory");
    asm volatile("barrier.cluster.wait.aligned;" ::: "memory");
}
__device__ __forceinline__ unsigned ctarank_() {
    unsigned r; asm("mov.u32 %0, %%cluster_ctarank;" : "=r"(r)); return r;
}

__global__ __launch_bounds__(NW * 32, 1) __cluster_dims__(NC, 1, 1)
void dtw_cluster3_kernel(const float* __restrict__ x,
                         const float* __restrict__ y,
                         float* __restrict__ out)
{
    __shared__ float ysp[3 * NLEN];        // ysp[NLEN + j] = y[j], pads = 0
    __shared__ float ring[NW][SRING];      // ring[w+1 local]: producer warp w (w<NW-1)
    __shared__ float bring[BRING];         // boundary ring: filled by upstream CTA (or +inf)
    __shared__ int   prog[NW + 2];         // [0]=upstream(remote), [1..NW]=local, [NW+1]=downstream(remote)

    const int t    = threadIdx.x;
    const int lane = t & 31;
    const int w    = t >> 5;
    const unsigned rank = ctarank_();
    const bool has_prev = (rank != 0);
    const bool has_next = (rank != NC - 1);

    for (int k = t; k < 3 * NLEN; k += NW * 32) {
        int j = k - NLEN;
        ysp[k] = ((unsigned)j < (unsigned)NLEN) ? y[j] : 0.0f;
    }
    for (int k = t; k < NW * SRING; k += NW * 32) (&ring[0][0])[k] = FINF;
    for (int k = t; k < BRING;      k += NW * 32) bring[k] = FINF;   // phantom upstream
    if (t < NW + 2) {
        int v = -1;
        if (t == 0      && !has_prev) v = 0x7fffffff;   // no upstream producer
        if (t == NW + 1 && !has_next) v = 0x7fffffff;   // no downstream consumer
        prog[t] = v;
    }

    const int i0 = (int)rank * 1024 + w * 128 + lane * RPT;

    float xv[RPT];
    {
        float4 a = reinterpret_cast<const float4*>(x + i0)[0];
        xv[0] = a.x; xv[1] = a.y; xv[2] = a.z; xv[3] = a.w;
    }

    float p[RPT], pp[RPT], yq[RPT];
    #pragma unroll
    for (int r = 0; r < RPT; ++r) { p[r] = FINF; pp[r] = FINF; }
    float dTop = (rank == 0 && t == 0) ? 0.0f : FINF;   // DTW[-1][-1]=0 seeds (0,0)

    unsigned rem_bring = 0, rem_prog0 = 0, rem_progN1 = 0;
    if (w == NW - 1 && has_next) {
        rem_bring = mapa_u32(smem_u32(&bring[0]), rank + 1);
        rem_prog0 = mapa_u32(smem_u32(&prog[0]),  rank + 1);
    }
    if (w == 0 && has_prev) {
        rem_progN1 = mapa_u32(smem_u32(&prog[NW + 1]), rank - 1);
    }

    cluster_sync_();   // smem init visible cluster-wide before any remote write

    const float* yb = ysp + NLEN - i0;
    yq[3] = yb[-1]; yq[2] = yb[-2]; yq[1] = yb[-3]; yq[0] = 0.0f;

    // Warp w consumes ring 'prev' (boundary ring for w==0), produces ring[w]
    // (for w<NW-1) or the remote boundary ring (w==NW-1 && has_next).
    const float* ringprev = (w == 0) ? bring : ring[w - 1];
    const unsigned prevmask = (w == 0) ? (BRING - 1) : (SRING - 1);
    float* ringself = (w < NW - 1) ? ring[w] : nullptr;

    const bool last_warp = (w == NW - 1);
    const bool v1_remote = has_prev && (w == 0);        // prog[w] remote-written
    const bool v2_remote = has_next && (w == NW - 1);   // prog[w+2] remote-written
    // Downstream slack: boundary producer gets the big ring, local warps SRING.
    const int  slack2 = v2_remote ? (BRING - 1) : (SRING - 1);

    #define STEP_BODY(u)                                                        \
        {                                                                       \
            const float yn = ybb[(u)];                                          \
            yq[(u) & 3] = yn;                                                   \
            float up = __shfl_up_sync(0xffffffffu, p[RPT - 1], 1);              \
            if (lane == 0) up = ((u) == 0) ? up_first : rpb[(u) - 1];           \
            float nv[RPT];                                                      \
            {                                                                   \
                const float dy = xv[0] - yn;                                    \
                nv[0] = fmaf(dy, dy, fminf(fminf(up, dTop), p[0]));             \
            }                                                                   \
            _Pragma("unroll")                                                   \
            for (int r = 1; r < RPT; ++r) {                                     \
                const float dy = xv[r] - yq[((u) - r) & 3];                     \
                nv[r] = fmaf(dy, dy, fminf(fminf(p[r - 1], pp[r - 1]), p[r]));  \
            }                                                                   \
            if (lane == 31) {                                                   \
                if (!last_warp)    rs[(u)] = nv[RPT - 1];                       \
                else if (has_next) st_f32_rem(rrs + (unsigned)((u) << 2), nv[RPT - 1]); \
            }                                                                   \
            dTop = up;                                                          \
            _Pragma("unroll")                                                   \
            for (int r = 0; r < RPT; ++r) { pp[r] = p[r]; p[r] = nv[r]; }       \
        }

    for (int m = 0; m <= NB; ++m) {
        const int d0    = m * KB;
        const int steps = (m == NB) ? TAIL : KB;
        const int need1 = d0 + steps - 2;          // upstream must have written this far
        const int need2 = d0 + steps - 1 - slack2; // downstream must be within ring slack

        int v1, v2;
        do {
            v1 = v1_remote ? ld_rlx_cluster(prog + w)     : ld_acq_cta(prog + w);
            v2 = v2_remote ? ld_rlx_cluster(prog + w + 2) : ld_acq_cta(prog + w + 2);
        } while (v1 < need1 || v2 < need2);
        if (v1_remote) fence_acq_cluster();   // pair with upstream's release (data ring)

        const float* ybb = yb + d0;
        const float* rpb = ringprev + (d0 & prevmask);          // KB-aligned: no wrap in batch
        const float  up_first = ringprev[(d0 - 1) & prevmask];  // wraps only at u==0
        float*       rs  = last_warp ? nullptr : (ringself + (d0 & (SRING - 1)));
        const unsigned rrs = rem_bring + (unsigned)((d0 & (BRING - 1)) << 2);

        if (m < NB) {
            #pragma unroll
            for (int u = 0; u < KB; ++u) STEP_BODY(u)
        } else {
            #pragma unroll
            for (int u = 0; u < TAIL; ++u) STEP_BODY(u)
        }

        const int done = d0 + steps - 1;
        if (lane == 31) {
            st_rel_cta(prog + w + 1, done);                                   // local chain
            if (last_warp && has_next) st_rel_cluster_rem(rem_prog0, done);   // notify downstream
            if (w == 0 && has_prev)    st_rel_cluster_rem(rem_progN1, done);  // backpressure up
        }
    }
    #undef STEP_BODY

    // Global last row 2047: CTA rank 1, warp 7, lane 31, r = 3.
    if (!has_next && t == NW * 32 - 1) out[0] = sqrtf(p[RPT - 1]);

    cluster_sync_();   // keep smem alive while a peer may still write into it
}

extern "C" void kernel_launch(void* const* d_in, const int* in_sizes, int n_in,
                              void* d_out, int out_size)
{
    const float* x = (const float*)d_in[0];
    const float* y = (const float*)d_in[1];
    float* out = (float*)d_out;
    dtw_cluster3_kernel<<<NC, NW * 32>>>(x, y, out);
}

// round 8
// speedup vs baseline: 1.8390x; 1.8390x over previous
#include <cuda_runtime.h>
#include <cuda_bf16.h>

// DTW 2048x2048 anti-diagonal wavefront, single CTA, 8 warps, 8 rows/thread.
// Proven R2 engine (warp-skew pipeline: smem ring + cta-scope acquire/release
// progress counters, 16-diagonal batches) with two instruction-count cuts:
//  1. min(a,b,c) via __vimin3_s32 on the float bit patterns: every DP value is
//     a sum of squares in [0, +inf] (no NaNs), where IEEE-754 ordering equals
//     signed-int ordering, so one VIMNMX3 (alu pipe) replaces two FMNMX.
//     8 ops/thread/step saved (32 -> 24 math slots).
//  2. y staged in a 5/4-padded smem layout phys(j) = j + (j>>2): per-step lane
//     stride becomes 10 words -> 2-way bank conflict instead of R2's 8-way.
//     Batch base index is always ≡ 0 (mod 4), so in the unrolled loop the
//     per-step offset u + (u>>2) is a compile-time constant (no extra ALU).
// Out-of-range cells stay +inf (left edge) or finite garbage that only flows
// rightward (right edge) -- never into valid cells; no predicates needed.

#define NLEN  2048
#define NW    8
#define RPT   8
#define KB    16
#define NB    255           // full batches (255*16 = 4080)
#define TAIL  15            // 4080 + 15 = 4095 diagonals
#define SRING 64
#define YPAD  7680          // phys(3*NLEN-1)+2 = 6143+1535+2
#define FINF  __int_as_float(0x7f800000)

__device__ __forceinline__ unsigned smem_u32(const void* p) {
    return (unsigned)__cvta_generic_to_shared(p);
}
__device__ __forceinline__ int ld_acq(const int* p) {
    int v; unsigned a = smem_u32(p);
    asm volatile("ld.acquire.cta.shared::cta.b32 %0, [%1];" : "=r"(v) : "r"(a) : "memory");
    return v;
}
__device__ __forceinline__ void st_rel(int* p, int v) {
    unsigned a = smem_u32(p);
    asm volatile("st.release.cta.shared::cta.b32 [%0], %1;" :: "r"(a), "r"(v) : "memory");
}
// min of three nonnegative floats (incl. +inf) via signed-int 3-input min.
__device__ __forceinline__ float fmin3_nn(float a, float b, float c) {
    int r = __vimin3_s32(__float_as_int(a), __float_as_int(b), __float_as_int(c));
    return __int_as_float(r);
}
__device__ __forceinline__ int physidx(int j) { return j + (j >> 2); }

__global__ __launch_bounds__(NW * 32, 1)
void dtw_min3_kernel(const float* __restrict__ x,
                     const float* __restrict__ y,
                     float* __restrict__ out)
{
    __shared__ float ypad[YPAD];           // ypad[phys(j)] = y[j-NLEN] (0 outside)
    __shared__ float ring[NW + 1][SRING];  // ring[w+1][d&63] = warp w bottom row at d
    __shared__ int   prog[NW + 2];

    const int t    = threadIdx.x;
    const int lane = t & 31;
    const int w    = t >> 5;

    for (int k = t; k < 3 * NLEN; k += NW * 32) {
        int j = k - NLEN;
        ypad[physidx(k)] = ((unsigned)j < (unsigned)NLEN) ? y[j] : 0.0f;
    }
    for (int k = t; k < (NW + 1) * SRING; k += NW * 32)
        (&ring[0][0])[k] = FINF;           // ring[0] = phantom producer (+inf)
    if (t < NW + 2)
        prog[t] = (t == 0 || t == NW + 1) ? 0x7fffffff : -1;

    const int i0 = w * 256 + lane * RPT;   // this thread's top row

    float xv[RPT];
    {
        float4 a = reinterpret_cast<const float4*>(x + i0)[0];
        float4 b = reinterpret_cast<const float4*>(x + i0)[1];
        xv[0]=a.x; xv[1]=a.y; xv[2]=a.z; xv[3]=a.w;
        xv[4]=b.x; xv[5]=b.y; xv[6]=b.z; xv[7]=b.w;
    }

    float p[RPT], pp[RPT], yq[8];
    #pragma unroll
    for (int r = 0; r < RPT; ++r) { p[r] = FINF; pp[r] = FINF; }
    float dTop = (t == 0) ? 0.0f : FINF;   // virtual DTW[-1][-1]=0 seeds (0,0)

    __syncthreads();

    const int yoff = NLEN - i0;            // y smem index for diagonal d is yoff + d
    yq[0] = 0.0f;
    #pragma unroll
    for (int k = 1; k <= 7; ++k) yq[(8 - k) & 7] = ypad[physidx(yoff - k)];

    const float* ringprev = ring[w];
    float*       ringself = ring[w + 1];

    for (int m = 0; m <= NB; ++m) {
        const int d0    = m * KB;
        const int steps = (m == NB) ? TAIL : KB;
        const int need1 = d0 + steps - 2;               // producer done through here
        const int need2 = d0 + steps - 1 - (SRING - 1); // consumer read ring this far
        int v1, v2;
        do { v1 = ld_acq(prog + w); v2 = ld_acq(prog + w + 2); }
        while (v1 < need1 || v2 < need2);

        // jb = yoff + d0 is ≡ 0 (mod 4)  =>  phys(jb + u) = pb + u + (u>>2).
        const int    jb  = yoff + d0;
        const float* ybb = ypad + (jb + (jb >> 2));
        float*       rs  = ringself + (d0 & (SRING - 1));    // no wrap within batch
        const float* rpb = ringprev + (d0 & (SRING - 1));
        const float  up_first = ringprev[(d0 - 1) & (SRING - 1)];  // wraps only at u=0

        #pragma unroll
        for (int u = 0; u < KB; ++u) {
            if (u >= steps) break;                        // trims only the tail batch
            const float yn = ybb[u + (u >> 2)];           // compile-time offset
            yq[u & 7] = yn;
            float up = __shfl_up_sync(0xffffffffu, p[RPT - 1], 1);
            if (lane == 0) up = (u == 0) ? up_first : rpb[u - 1];

            float nv[RPT];
            {
                const float dy = xv[0] - yn;
                nv[0] = fmaf(dy, dy, fmin3_nn(up, dTop, p[0]));
            }
            #pragma unroll
            for (int r = 1; r < RPT; ++r) {
                const float dy = xv[r] - yq[(u - r) & 7];
                nv[r] = fmaf(dy, dy, fmin3_nn(p[r-1], pp[r-1], p[r]));
            }
            if (lane == 31) rs[u] = nv[RPT - 1];

            dTop = up;
            #pragma unroll
            for (int r = 0; r < RPT; ++r) { pp[r] = p[r]; p[r] = nv[r]; }
        }

        if (lane == 31) st_rel(prog + w + 1, d0 + steps - 1);
    }

    // Warp 7, lane 31, bottom row 2047: value at d = 4094 is p[7] after rotation.
    if (t == NW * 32 - 1) out[0] = sqrtf(p[RPT - 1]);
}

extern "C" void kernel_launch(void* const* d_in, const int* in_sizes, int n_in,
                              void* d_out, int out_size)
{
    const float* x = (const float*)d_in[0];
    const float* y = (const float*)d_in[1];
    float* out = (float*)d_out;
    dtw_min3_kernel<<<1, NW * 32>>>(x, y, out);
}

// round 11
// speedup vs baseline: 1.9412x; 1.0556x over previous
#include <cuda_runtime.h>
#include <cuda_bf16.h>

// DTW 2048x2048 anti-diagonal wavefront, single CTA, 8 warps, 8 rows/thread.
// R8 engine (warp-skew pipeline, smem ring + cta-scope acquire/release
// counters, 16-diag batches, VIMNMX3 3-input min) with ALL per-step memory
// ops hoisted out of the inner loop:
//  * y: 24-value register window prefetched per batch (6 aligned LDS.128);
//    in-loop access is a compile-time register index.
//  * ring (consumer): bu[0..15] prefetched per batch (4 broadcast LDS.128
//    for slots d0..d0+15 -- safe: those slots can't be overwritten until our
//    own progress publishes -- plus 1 scalar LDS for d0-1).
//  * ring (producer): nv[7] accumulated in a float4, one predicated lane31
//    STS.128 every 4 steps instead of a scalar STS every step.
// Inner loop per step: 1 shfl (only MIO op) + SEL + 8 FADD + 8 VIMNMX3 +
// 8 FFMA. Out-of-range cells stay +inf (left edge) or finite garbage that
// only flows rightward (right edge) -- never into valid cells.

#define NLEN  2048
#define NW    8
#define RPT   8
#define KB    16
#define NB    255           // full batches (255*16 = 4080)
#define TAIL  15            // 4080 + 15 = 4095 diagonals
#define SRING 64
#define FINF  __int_as_float(0x7f800000)

__device__ __forceinline__ unsigned smem_u32(const void* p) {
    return (unsigned)__cvta_generic_to_shared(p);
}
__device__ __forceinline__ int ld_acq(const int* p) {
    int v; unsigned a = smem_u32(p);
    asm volatile("ld.acquire.cta.shared::cta.b32 %0, [%1];" : "=r"(v) : "r"(a) : "memory");
    return v;
}
__device__ __forceinline__ void st_rel(int* p, int v) {
    unsigned a = smem_u32(p);
    asm volatile("st.release.cta.shared::cta.b32 [%0], %1;" :: "r"(a), "r"(v) : "memory");
}
__device__ __forceinline__ void lds128(float& a, float& b, float& c, float& d, unsigned addr) {
    asm volatile("ld.shared.v4.f32 {%0,%1,%2,%3}, [%4];"
                 : "=f"(a), "=f"(b), "=f"(c), "=f"(d) : "r"(addr));
}
// min of three nonnegative floats (incl. +inf): IEEE order == signed-int order.
__device__ __forceinline__ float fmin3_nn(float a, float b, float c) {
    int r = __vimin3_s32(__float_as_int(a), __float_as_int(b), __float_as_int(c));
    return __int_as_float(r);
}

__global__ __launch_bounds__(NW * 32, 1)
void dtw_reg_kernel(const float* __restrict__ x,
                    const float* __restrict__ y,
                    float* __restrict__ out)
{
    __shared__ float ysp[3 * NLEN];                      // ysp[NLEN+j] = y[j], pads 0
    __shared__ __align__(16) float ring[NW + 1][SRING];  // ring[w+1][d&63] = warp w bottom row at d
    __shared__ int prog[NW + 2];

    const int t    = threadIdx.x;
    const int lane = t & 31;
    const int w    = t >> 5;

    for (int k = t; k < 3 * NLEN; k += NW * 32) {
        int j = k - NLEN;
        ysp[k] = ((unsigned)j < (unsigned)NLEN) ? y[j] : 0.0f;
    }
    for (int k = t; k < (NW + 1) * SRING; k += NW * 32)
        (&ring[0][0])[k] = FINF;           // ring[0] = phantom producer (+inf)
    if (t < NW + 2)
        prog[t] = (t == 0 || t == NW + 1) ? 0x7fffffff : -1;

    const int i0 = w * 256 + lane * RPT;   // this thread's top row

    float xv[RPT];
    {
        float4 a = reinterpret_cast<const float4*>(x + i0)[0];
        float4 b = reinterpret_cast<const float4*>(x + i0)[1];
        xv[0]=a.x; xv[1]=a.y; xv[2]=a.z; xv[3]=a.w;
        xv[4]=b.x; xv[5]=b.y; xv[6]=b.z; xv[7]=b.w;
    }

    float p[RPT], pp[RPT];
    #pragma unroll
    for (int r = 0; r < RPT; ++r) { p[r] = FINF; pp[r] = FINF; }
    float dTop = (t == 0) ? 0.0f : FINF;   // virtual DTW[-1][-1]=0 seeds (0,0)

    __syncthreads();

    // y smem address for window base (d0 - 8): yoff + d0 - 8, 16B aligned
    // (yoff = NLEN - i0 is a multiple of 8, d0 a multiple of 16).
    const unsigned ybase = smem_u32(ysp) + (unsigned)((NLEN - i0 - 8) << 2);
    const unsigned rpadd = smem_u32(&ring[w][0]);
    float* ringself = ring[w + 1];

    // Step body: yv[] / bu[] indices are compile-time constants under unroll.
    #define STEP_CORE(u)                                                        \
        float up = __shfl_up_sync(0xffffffffu, p[RPT - 1], 1);                  \
        if (lane == 0) up = ((u) == 0) ? up_first : bu[(u) - 1];                \
        float nv[RPT];                                                          \
        {                                                                       \
            const float dy = xv[0] - yv[8 + (u)];                               \
            nv[0] = fmaf(dy, dy, fmin3_nn(up, dTop, p[0]));                     \
        }                                                                       \
        _Pragma("unroll")                                                       \
        for (int r = 1; r < RPT; ++r) {                                         \
            const float dy = xv[r] - yv[8 + (u) - r];                           \
            nv[r] = fmaf(dy, dy, fmin3_nn(p[r-1], pp[r-1], p[r]));              \
        }                                                                       \
        dTop = up;                                                              \
        _Pragma("unroll")                                                       \
        for (int r = 0; r < RPT; ++r) { pp[r] = p[r]; p[r] = nv[r]; }

    for (int m = 0; m <= NB; ++m) {
        const int d0 = m * KB;
        const bool full = (m < NB);
        const int steps = full ? KB : TAIL;
        const int need1 = d0 + steps - 2;               // producer wrote through here
        const int need2 = d0 + steps - 1 - (SRING - 1); // our consumer read this far
        int v1, v2;
        do { v1 = ld_acq(prog + w); v2 = ld_acq(prog + w + 2); }
        while (v1 < need1 || v2 < need2);

        // Ring prefetch (after acquire): bu[k] = prev-warp value at diagonal d0+k.
        // Slots d0.. can't be recycled until our own prog publishes => race-free.
        float bu[16];
        {
            const unsigned s = (unsigned)(d0 & (SRING - 1)) << 2;   // no wrap in batch
            lds128(bu[0],  bu[1],  bu[2],  bu[3],  rpadd + s);
            lds128(bu[4],  bu[5],  bu[6],  bu[7],  rpadd + s + 16);
            lds128(bu[8],  bu[9],  bu[10], bu[11], rpadd + s + 32);
            lds128(bu[12], bu[13], bu[14], bu[15], rpadd + s + 48);
        }
        const float up_first = ring[w][(d0 - 1) & (SRING - 1)];

        // y prefetch: yv[k] = y value for diagonal d0 + k - 8 (thread-relative).
        float yv[24];
        {
            const unsigned b = ybase + (unsigned)(d0 << 2);
            #pragma unroll
            for (int v = 0; v < 6; ++v)
                lds128(yv[4*v], yv[4*v+1], yv[4*v+2], yv[4*v+3], b + 16u * v);
        }

        float* rs = ringself + (d0 & (SRING - 1));

        if (full) {
            float4 b4;
            #pragma unroll
            for (int u = 0; u < KB; ++u) {
                STEP_CORE(u)
                if ((u & 3) == 0) b4.x = nv[RPT-1];
                if ((u & 3) == 1) b4.y = nv[RPT-1];
                if ((u & 3) == 2) b4.z = nv[RPT-1];
                if ((u & 3) == 3) {
                    b4.w = nv[RPT-1];
                    if (lane == 31) *reinterpret_cast<float4*>(rs + (u - 3)) = b4;
                }
            }
        } else {
            #pragma unroll
            for (int u = 0; u < TAIL; ++u) {
                STEP_CORE(u)
                if (lane == 31) rs[u] = nv[RPT-1];   // tail: scalar stores, runs once
            }
        }

        if (lane == 31) st_rel(prog + w + 1, d0 + steps - 1);
    }
    #undef STEP_CORE

    // Warp 7, lane 31, bottom row 2047: value at d = 4094 is p[7] after rotation.
    if (t == NW * 32 - 1) out[0] = sqrtf(p[RPT - 1]);
}

extern "C" void kernel_launch(void* const* d_in, const int* in_sizes, int n_in,
                              void* d_out, int out_size)
{
    const float* x = (const float*)d_in[0];
    const float* y = (const float*)d_in[1];
    float* out = (float*)d_out;
    dtw_reg_kernel<<<1, NW * 32>>>(x, y, out);
}